// round 6
// baseline (speedup 1.0000x reference)
#include <cuda_runtime.h>
#include <cstdint>

#define THREADS 512   // 64 query-quads x 8 candidate-chunks
#define NCHUNK  8
#define QPT     4     // queries per thread

// Packed-fp32x2 helpers (sm_103a). Per-lane .rn rounding is bit-identical to
// scalar ops, preserving argmin bit-exactness vs the JAX reference.
#define MUL2(d, a, b) \
    asm("mul.rn.f32x2 %0, %1, %2;" : "=l"(d) : "l"(a), "l"(b))
#define ADD2(d, a, b) \
    asm("add.rn.f32x2 %0, %1, %2;" : "=l"(d) : "l"(a), "l"(b))
#define FMA2(d, a, b, c) \
    asm("fma.rn.f32x2 %0, %1, %2, %3;" : "=l"(d) : "l"(a), "l"(b), "l"(c))

__device__ __forceinline__ unsigned long long pack2(float lo, float hi) {
    unsigned long long r;
    asm("mov.b64 %0, {%1, %2};" : "=l"(r) : "f"(lo), "f"(hi));
    return r;
}
__device__ __forceinline__ void unpack2(float& lo, float& hi,
                                        unsigned long long v) {
    asm("mov.b64 {%0, %1}, %2;" : "=f"(lo), "=f"(hi) : "l"(v));
}

// Chamfer distance, both directions fused via blockIdx.z.
// Candidates cached in smem in pair-SoA layout, viewed as ulonglong2 so each
// LDS.128 register quad IS two packed f32x2 operands (no pack MOVs):
//   sh2[2p]   = ((x0,x1),(y0,y1))
//   sh2[2p+1] = ((z0,z1),(w0,w1))   w = |c|^2 with reference rounding
// Each thread owns FOUR queries and scans one of 8 candidate chunks (1024
// candidates): every load amortized over 4 evals, 4 independent FMA chains.
__global__ __launch_bounds__(THREADS, 1)
void chamfer_kernel(const float* __restrict__ xyz1,
                    const float* __restrict__ xyz2,
                    float* __restrict__ out,
                    int N, int M, int B) {
    extern __shared__ float4 sh[];
    __shared__ float2 red[QPT][THREADS];   // per-query-slot (best, idx)

    const int dir = blockIdx.z;
    const int b   = blockIdx.y;

    const float* q;
    const float* c;
    int Nq, Nc;
    float* dist_out;
    float* idx_out;
    if (dir == 0) {
        q = xyz1; c = xyz2; Nq = N; Nc = M;
        dist_out = out;                                        // dist1
        idx_out  = out + (size_t)B * (N + M);                  // idx1
    } else {
        q = xyz2; c = xyz1; Nq = M; Nc = N;
        dist_out = out + (size_t)B * N;                        // dist2
        idx_out  = out + (size_t)B * (N + M) + (size_t)B * N;  // idx2
    }

    // ---- fill shared memory (pair layout), reference rounding for |c|^2 ----
    const float* cb = c + (size_t)b * Nc * 3;
    const int npairs = Nc >> 1;
    for (int p = threadIdx.x; p < npairs; p += THREADS) {
        float x0 = cb[6 * p + 0], y0 = cb[6 * p + 1], z0 = cb[6 * p + 2];
        float x1 = cb[6 * p + 3], y1 = cb[6 * p + 4], z1 = cb[6 * p + 5];
        float w0 = __fadd_rn(__fadd_rn(__fmul_rn(x0, x0), __fmul_rn(y0, y0)),
                             __fmul_rn(z0, z0));
        float w1 = __fadd_rn(__fadd_rn(__fmul_rn(x1, x1), __fmul_rn(y1, y1)),
                             __fmul_rn(z1, z1));
        sh[2 * p]     = make_float4(x0, x1, y0, y1);
        sh[2 * p + 1] = make_float4(z0, z1, w0, w1);
    }
    __syncthreads();

    const ulonglong2* sh2 = reinterpret_cast<const ulonglong2*>(sh);

    const int g     = threadIdx.x & 63;    // query-quad id (0..63)
    const int chunk = threadIdx.x >> 6;    // candidate chunk (0..7)

    // four query lanes for this thread (interleaved across CTAs for balance)
    float ax[QPT], ay[QPT], az[QPT], sq[QPT];
    unsigned long long AX[QPT], AY[QPT], AZ[QPT], SQ[QPT];
#pragma unroll
    for (int k = 0; k < QPT; k++) {
        const int lane = QPT * g + k;
        const int i = lane * gridDim.x + blockIdx.x;
        const int iq = (i < Nq) ? i : 0;
        const float* qp = q + ((size_t)b * Nq + iq) * 3;
        ax[k] = qp[0]; ay[k] = qp[1]; az[k] = qp[2];
        sq[k] = __fadd_rn(__fadd_rn(__fmul_rn(ax[k], ax[k]),
                                    __fmul_rn(ay[k], ay[k])),
                          __fmul_rn(az[k], az[k]));
        AX[k] = pack2(ax[k], ax[k]); AY[k] = pack2(ay[k], ay[k]);
        AZ[k] = pack2(az[k], az[k]); SQ[k] = pack2(sq[k], sq[k]);
    }
    const unsigned long long M22 = pack2(-2.0f, -2.0f);

    const int csz   = Nc / NCHUNK;         // 1024
    const int cbase = chunk * csz;

    float best[QPT];
    int   bj[QPT];
#pragma unroll
    for (int k = 0; k < QPT; k++) { best[k] = 3.402823466e38f; bj[k] = cbase; }

    for (int j = cbase; j < cbase + csz; j += 8) {
        float e[QPT][8];
#pragma unroll
        for (int p = 0; p < 4; p++) {
            ulonglong2 A2 = sh2[j + 2 * p];      // (x0,x1),(y0,y1)
            ulonglong2 B2 = sh2[j + 2 * p + 1];  // (z0,z1),(w0,w1)
#pragma unroll
            for (int k = 0; k < QPT; k++) {
                unsigned long long t0, t1, t2, s2, r2;
                MUL2(t0, A2.x, AX[k]);
                FMA2(t1, A2.y, AY[k], t0);
                FMA2(t2, B2.x, AZ[k], t1);
                ADD2(s2, SQ[k], B2.y);
                FMA2(r2, M22, t2, s2);
                unpack2(e[k][2 * p], e[k][2 * p + 1], r2);
            }
        }
#pragma unroll
        for (int k = 0; k < QPT; k++) {
            float m01 = fminf(e[k][0], e[k][1]);
            float m23 = fminf(e[k][2], e[k][3]);
            float m45 = fminf(e[k][4], e[k][5]);
            float m67 = fminf(e[k][6], e[k][7]);
            float m03 = fminf(m01, m23);
            float m47 = fminf(m45, m67);
            float bm  = fminf(m03, m47);
            if (bm < best[k]) bj[k] = j;   // strict < : earliest block wins
            best[k] = fminf(best[k], bm);
        }
    }

    // ---- recover index within each winning block (first occurrence) ----
#pragma unroll
    for (int k = 0; k < QPT; k++) {
        int kwin = 0;
#pragma unroll
        for (int kk = 7; kk >= 0; kk--) {
            int p = kk >> 1, lane = kk & 1;
            float4 A  = sh[bj[k] + 2 * p];
            float4 Bv = sh[bj[k] + 2 * p + 1];
            float cx = lane ? A.y  : A.x;
            float cy = lane ? A.w  : A.z;
            float cz = lane ? Bv.y : Bv.x;
            float cw = lane ? Bv.w : Bv.z;
            float cr = fmaf(cz, az[k], fmaf(cy, ay[k], __fmul_rn(cx, ax[k])));
            float ek = fmaf(-2.0f, cr, __fadd_rn(sq[k], cw));
            if (ek == best[k]) kwin = kk;  // descending: smallest k survives
        }
        red[k][threadIdx.x] = make_float2(best[k], (float)(bj[k] + kwin));
    }
    __syncthreads();

    // ---- merge the 8 chunks; ascending chunk order, strict < keeps the
    //      earliest chunk (smaller candidate index) on exact ties ----------
    if (threadIdx.x < 256) {
        const int l  = threadIdx.x;        // query lane 0..255
        const int qi = l * gridDim.x + blockIdx.x;
        if (qi < Nq) {
            const int qk = l & (QPT - 1);  // query slot within the quad
            const int gg = l / QPT;        // quad id
            float2 r = red[qk][gg];        // chunk 0
#pragma unroll
            for (int cth = 1; cth < NCHUNK; cth++) {
                float2 rc = red[qk][cth * 64 + gg];
                if (rc.x < r.x) r = rc;
            }
            dist_out[(size_t)b * Nq + qi] = r.x;
            idx_out [(size_t)b * Nq + qi] = r.y;
        }
    }
}

extern "C" void kernel_launch(void* const* d_in, const int* in_sizes, int n_in,
                              void* d_out, int out_size) {
    const float* xyz1 = (const float*)d_in[0];
    const float* xyz2 = (const float*)d_in[1];
    float* out = (float*)d_out;

    const int B = 2;
    const int N = in_sizes[0] / (3 * B);
    const int M = in_sizes[1] / (3 * B);
    const int maxNM = (N > M) ? N : M;

    const size_t shmem = (size_t)maxNM * sizeof(float4);  // 128 KB for 8192
    cudaFuncSetAttribute(chamfer_kernel,
                         cudaFuncAttributeMaxDynamicSharedMemorySize,
                         (int)shmem);

    // 37 * 2 * 2 = 148 CTAs: one per SM, queries interleaved for balance.
    dim3 grid(37, B, 2);
    chamfer_kernel<<<grid, THREADS, shmem>>>(xyz1, xyz2, out, N, M, B);
}